// round 14
// baseline (speedup 1.0000x reference)
#include <cuda_runtime.h>
#include <math.h>

#define BB 2
#define NN 2048
#define DD 256
#define MROWS (BB*NN)

typedef unsigned long long u64;
__device__ __forceinline__ u64 pk2(float lo, float hi) {
    u64 r; asm("mov.b64 %0,{%1,%2};" : "=l"(r) : "f"(lo), "f"(hi)); return r;
}
__device__ __forceinline__ void fma2(u64& d, u64 a, u64 b) {
    asm("fma.rn.f32x2 %0,%1,%2,%0;" : "+l"(d) : "l"(a), "l"(b));
}
__device__ __forceinline__ float2 up2(u64 v) {
    float lo, hi; asm("mov.b64 {%0,%1},%2;" : "=f"(lo), "=f"(hi) : "l"(v));
    float2 f; f.x = lo; f.y = hi; return f;
}

__device__ float g_qp[MROWS*DD];
__device__ float g_kp[MROWS*DD];
__device__ float g_vp[MROWS*DD];
__device__ float g_av[MROWS*DD];
__device__ float g_y [MROWS*DD];
__device__ float g_wc[DD*DD];
__device__ float g_bc[DD];

/* R5-proven 64x64 GEMM body: C = A@W^T + bias */
__device__ __forceinline__ void gemm_body(const float* __restrict__ A,
    const float* __restrict__ W, const float* __restrict__ bias,
    float* __restrict__ C, int K, int Nc)
{
    __shared__ float As[16*68], Bs[16*68];
    const int t = threadIdx.x;
    const int row0 = blockIdx.y * 64, col0 = blockIdx.x * 64;
    const int fr = t >> 2, fc = (t & 3) << 2;
    const int ty = t >> 4, tx = t & 15;
    u64 acc[4][2] = {};
    for (int k0 = 0; k0 < K; k0 += 16) {
        float4 a4 = *(const float4*)&A[(size_t)(row0+fr)*K + k0+fc];
        float4 w4 = *(const float4*)&W[(size_t)(col0+fr)*K + k0+fc];
        As[(fc+0)*68+fr]=a4.x; As[(fc+1)*68+fr]=a4.y; As[(fc+2)*68+fr]=a4.z; As[(fc+3)*68+fr]=a4.w;
        Bs[(fc+0)*68+fr]=w4.x; Bs[(fc+1)*68+fr]=w4.y; Bs[(fc+2)*68+fr]=w4.z; Bs[(fc+3)*68+fr]=w4.w;
        __syncthreads();
#pragma unroll
        for (int kk = 0; kk < 16; kk++) {
            float4 a = *(float4*)&As[kk*68 + (ty<<2)];
            ulonglong2 bb = *(ulonglong2*)&Bs[kk*68 + (tx<<2)];
            float av_[4]={a.x,a.y,a.z,a.w};
#pragma unroll
            for (int i=0;i<4;i++) {
                u64 aa = pk2(av_[i], av_[i]);
                fma2(acc[i][0], aa, bb.x);
                fma2(acc[i][1], aa, bb.y);
            }
        }
        __syncthreads();
    }
    const float4 bb = *(const float4*)&bias[col0 + (tx<<2)];
#pragma unroll
    for (int i=0;i<4;i++) {
        float2 c01 = up2(acc[i][0]), c23 = up2(acc[i][1]);
        float4 o = {c01.x+bb.x, c01.y+bb.y, c23.x+bb.z, c23.y+bb.w};
        *(float4*)&C[(size_t)(row0+(ty<<2)+i)*Nc + col0 + (tx<<2)] = o;
    }
}

/* Wc = Wfc1[:, :256] @ Wfc ; block (0,0) also computes bc */
__device__ __forceinline__ void wcomb_body(
    const float* __restrict__ Wfc1, const float* __restrict__ Wfc,
    const float* __restrict__ bfc, const float* __restrict__ bfc1,
    float* __restrict__ wc, float* __restrict__ bc)
{
    __shared__ float As[16*68], Bs[16*68];
    const int t = threadIdx.x;
    const int row0 = blockIdx.y*64, col0 = blockIdx.x*64;
    const int fr = t >> 2, fc = (t & 3) << 2;
    const int kr = t >> 4, cc = (t & 15) << 2;
    const int ty = t >> 4, tx = t & 15;
    u64 acc[4][2] = {};
    for (int k0 = 0; k0 < DD; k0 += 16) {
        float4 a4 = *(const float4*)&Wfc1[(size_t)(row0+fr)*(2*DD) + k0+fc];
        float4 b4 = *(const float4*)&Wfc[(size_t)(k0+kr)*DD + col0+cc];
        As[(fc+0)*68+fr]=a4.x; As[(fc+1)*68+fr]=a4.y; As[(fc+2)*68+fr]=a4.z; As[(fc+3)*68+fr]=a4.w;
        Bs[kr*68+cc+0]=b4.x; Bs[kr*68+cc+1]=b4.y; Bs[kr*68+cc+2]=b4.z; Bs[kr*68+cc+3]=b4.w;
        __syncthreads();
#pragma unroll
        for (int kk = 0; kk < 16; kk++) {
            float4 a = *(float4*)&As[kk*68 + (ty<<2)];
            ulonglong2 bb = *(ulonglong2*)&Bs[kk*68 + (tx<<2)];
            float av_[4]={a.x,a.y,a.z,a.w};
#pragma unroll
            for (int i=0;i<4;i++) {
                u64 aa = pk2(av_[i], av_[i]);
                fma2(acc[i][0], aa, bb.x);
                fma2(acc[i][1], aa, bb.y);
            }
        }
        __syncthreads();
    }
#pragma unroll
    for (int i=0;i<4;i++) {
        float2 c01 = up2(acc[i][0]), c23 = up2(acc[i][1]);
        float4 o = {c01.x, c01.y, c23.x, c23.y};
        *(float4*)&wc[(size_t)(row0+(ty<<2)+i)*DD + col0 + (tx<<2)] = o;
    }
    if (blockIdx.x == 0 && blockIdx.y == 0) {
        float s = bfc1[t];
        for (int k = 0; k < DD; k += 4) {
            float4 w = *(const float4*)&Wfc1[(size_t)t*(2*DD) + k];
            float4 b = *(const float4*)&bfc[k];
            s += w.x*b.x + w.y*b.y + w.z*b.z + w.w*b.w;
        }
        bc[t] = s;
    }
}

/* z=0..2: q/k/v projections; z=3 (blockIdx.y<4): Wc combine */
__global__ __launch_bounds__(256) void gemm_qkv_k(
    const float* __restrict__ q, const float* __restrict__ k, const float* __restrict__ v,
    const float* __restrict__ Wq, const float* __restrict__ bq,
    const float* __restrict__ Wk, const float* __restrict__ bk,
    const float* __restrict__ Wv, const float* __restrict__ bv,
    const float* __restrict__ Wfc1, const float* __restrict__ Wfc,
    const float* __restrict__ bfc, const float* __restrict__ bfc1,
    float* __restrict__ qp, float* __restrict__ kp, float* __restrict__ vp,
    float* __restrict__ wc, float* __restrict__ bc)
{
    if (blockIdx.z == 3) {
        if (blockIdx.y < 4)
            wcomb_body(Wfc1, Wfc, bfc, bfc1, wc, bc);
        return;
    }
    const float *A, *W, *bias; float* C;
    if (blockIdx.z == 0) { A=q; W=Wq; bias=bq; C=qp; }
    else if (blockIdx.z == 1) { A=k; W=Wk; bias=bk; C=kp; }
    else { A=v; W=Wv; bias=bv; C=vp; }
    gemm_body(A, W, bias, C, DD, DD);
}

/* y = av@wc^T + q@Wfc1[:,256:]^T + bc (K=512) */
__global__ __launch_bounds__(256) void gemm_fin_k(
    const float* __restrict__ av, const float* __restrict__ q,
    const float* __restrict__ wc, const float* __restrict__ Wfc1,
    const float* __restrict__ bc, float* __restrict__ y)
{
    __shared__ float As[16*68], Bs[16*68];
    const int t = threadIdx.x;
    const int row0 = blockIdx.y * 64, col0 = blockIdx.x * 64;
    const int fr = t >> 2, fc = (t & 3) << 2;
    const int ty = t >> 4, tx = t & 15;
    u64 acc[4][2] = {};
    for (int k0 = 0; k0 < 2*DD; k0 += 16) {
        float4 a4, w4;
        if (k0 < DD) {
            a4 = *(const float4*)&av[(size_t)(row0+fr)*DD + k0+fc];
            w4 = *(const float4*)&wc[(size_t)(col0+fr)*DD + k0+fc];
        } else {
            a4 = *(const float4*)&q[(size_t)(row0+fr)*DD + (k0-DD)+fc];
            w4 = *(const float4*)&Wfc1[(size_t)(col0+fr)*(2*DD) + k0+fc];
        }
        As[(fc+0)*68+fr]=a4.x; As[(fc+1)*68+fr]=a4.y; As[(fc+2)*68+fr]=a4.z; As[(fc+3)*68+fr]=a4.w;
        Bs[(fc+0)*68+fr]=w4.x; Bs[(fc+1)*68+fr]=w4.y; Bs[(fc+2)*68+fr]=w4.z; Bs[(fc+3)*68+fr]=w4.w;
        __syncthreads();
#pragma unroll
        for (int kk = 0; kk < 16; kk++) {
            float4 a = *(float4*)&As[kk*68 + (ty<<2)];
            ulonglong2 bb = *(ulonglong2*)&Bs[kk*68 + (tx<<2)];
            float av_[4]={a.x,a.y,a.z,a.w};
#pragma unroll
            for (int i=0;i<4;i++) {
                u64 aa = pk2(av_[i], av_[i]);
                fma2(acc[i][0], aa, bb.x);
                fma2(acc[i][1], aa, bb.y);
            }
        }
        __syncthreads();
    }
    const float4 bb = *(const float4*)&bc[col0 + (tx<<2)];
#pragma unroll
    for (int i=0;i<4;i++) {
        float2 c01 = up2(acc[i][0]), c23 = up2(acc[i][1]);
        float4 o = {c01.x+bb.x, c01.y+bb.y, c23.x+bb.z, c23.y+bb.w};
        *(float4*)&y[(size_t)(row0+(ty<<2)+i)*DD + col0 + (tx<<2)] = o;
    }
}

/* Sparse attention, dense single-pass output, pipelined pass-1. */
#define MAXC 256
__global__ __launch_bounds__(256) void sattn_k(
    const float* __restrict__ qp, const float* __restrict__ kp,
    const float* __restrict__ vp, const float* __restrict__ adj,
    float* __restrict__ attn, float* __restrict__ av)
{
    __shared__ unsigned short sidx[NN];
    __shared__ float ssc[8][MAXC];
    __shared__ float pbuf[8][MAXC];
    __shared__ int warp_tot[8];
    __shared__ int s_cnt;

    const int t = threadIdx.x, lane = t & 31, w = t >> 5;
    const int grow = blockIdx.x;
    const int b = grow >> 11, row = grow & 2047;
    const float invT = 0.17677669529663687f;

    /* ordered compaction of adj-row nonzeros (sidx ascending) */
    {
        const float* arow = adj + (size_t)b*NN*NN + (size_t)row*NN;
        float4 a0 = *(const float4*)&arow[t*8];
        float4 a1 = *(const float4*)&arow[t*8 + 4];
        float va[8] = {a0.x,a0.y,a0.z,a0.w,a1.x,a1.y,a1.z,a1.w};
        int c = 0;
#pragma unroll
        for (int e = 0; e < 8; e++) c += (va[e] > 0.f);
        int sc = c;
#pragma unroll
        for (int off = 1; off < 32; off <<= 1) {
            int vsh = __shfl_up_sync(0xffffffffu, sc, off);
            if (lane >= off) sc += vsh;
        }
        int excl = sc - c;
        if (lane == 31) warp_tot[w] = sc;
        __syncthreads();
        int base = 0;
#pragma unroll
        for (int i = 0; i < 8; i++) if (i < w) base += warp_tot[i];
        int pos = base + excl;
#pragma unroll
        for (int e = 0; e < 8; e++)
            if (va[e] > 0.f) sidx[pos++] = (unsigned short)(t*8 + e);
        if (t == 0) {
            int tot = 0;
#pragma unroll
            for (int i = 0; i < 8; i++) tot += warp_tot[i];
            s_cnt = tot;
        }
        __syncthreads();
    }
    const int cnt = s_cnt;
    const int h = w;
    float* arow_out = attn + ((size_t)(h*BB + b)*NN + row)*NN;
    const float* qrow = &qp[((size_t)(b*NN + row))*DD + h*32];

    if (cnt == 0) {
        const float u = 1.0f/2048.0f;
        float4 uv = {u,u,u,u};
#pragma unroll
        for (int i = 0; i < 16; i++)
            *(float4*)&arow_out[(i*32 + lane)*4] = uv;
        float o = 0.f;
        for (int j = 0; j < NN; j++)
            o += vp[((size_t)(b*NN + j))*DD + h*32 + lane];
        av[((size_t)(b*NN + row))*DD + h*32 + lane] = o * u;
        return;
    }

    const bool fast = (cnt <= MAXC);
    if (!fast) {
        float4 z4 = {0.f,0.f,0.f,0.f};
#pragma unroll
        for (int i = 0; i < 16; i++)
            *(float4*)&arow_out[(i*32 + lane)*4] = z4;
        __syncwarp();
    }

    /* pass 1 (pipelined): 8 lanes/neighbor, 4 neighbors/iter; prefetch next k */
    const int sub = lane >> 3;
    const int dg  = (lane & 7) << 2;
    const float4 qq = *(const float4*)&qrow[dg];
    float m = -1e30f, l = 0.f;

    int jcur = sub;
    bool okc = (jcur < cnt);
    int nc = sidx[okc ? jcur : 0];
    float4 kv = *(const float4*)&kp[((size_t)(b*NN + nc))*DD + h*32 + dg];

    for (int base = 0; base < cnt; base += 4) {
        int jn = base + 4 + sub;
        bool okn = (jn < cnt);
        float4 kvn = kv;
        if (base + 4 < cnt) {
            int nn = sidx[okn ? jn : 0];
            kvn = *(const float4*)&kp[((size_t)(b*NN + nn))*DD + h*32 + dg];
        }
        float part = qq.x*kv.x + qq.y*kv.y + qq.z*kv.z + qq.w*kv.w;
        part += __shfl_xor_sync(0xffffffffu, part, 4);
        part += __shfl_xor_sync(0xffffffffu, part, 2);
        part += __shfl_xor_sync(0xffffffffu, part, 1);
        if (okc && (lane & 7) == 0) {
            float s = part * invT;
            if (fast) ssc[w][jcur] = s; else arow_out[nc] = s;
            float mn = fmaxf(m, s);
            l = l*__expf(m - mn) + __expf(s - mn);
            m = mn;
        }
        jcur = jn; okc = okn; kv = kvn;
        nc = sidx[okc ? jcur : 0];
    }
#pragma unroll
    for (int off = 16; off >= 1; off >>= 1) {
        float om = __shfl_xor_sync(0xffffffffu, m, off);
        float ol = __shfl_xor_sync(0xffffffffu, l, off);
        float mn = fmaxf(m, om);
        l = l*__expf(m - mn) + ol*__expf(om - mn);
        m = mn;
    }
    const float rinv = 1.0f / l;
    __syncwarp();

    /* pass 2: probabilities */
    if (fast) {
        for (int j = lane; j < cnt; j += 32)
            ssc[w][j] = __expf(ssc[w][j] - m) * rinv;
    } else {
        for (int j = lane; j < cnt; j += 32) {
            int n = sidx[j];
            arow_out[n] = __expf(arow_out[n] - m) * rinv;
        }
    }
    __syncwarp();

    /* P@V from compact probs */
    float o = 0.f;
    for (int base = 0; base < cnt; base += 32) {
        int j = base + lane;
        float p = 0.f; int n = 0;
        if (j < cnt) {
            n = sidx[j];
            p = fast ? ssc[w][j] : arow_out[n];
        }
#pragma unroll 4
        for (int jj = 0; jj < 32; jj++) {
            if (base + jj >= cnt) break;
            float pb = __shfl_sync(0xffffffffu, p, jj);
            int   nb = __shfl_sync(0xffffffffu, n, jj);
            o += pb * vp[((size_t)(b*NN + nb))*DD + h*32 + lane];
        }
    }
    av[((size_t)(b*NN + row))*DD + h*32 + lane] = o;

    /* dense single-pass output: sorted pointer walk over spans */
    if (fast) {
        float4 z4 = {0.f,0.f,0.f,0.f};
        int jptr = 0;
        for (int span = 0; span < NN/MAXC; span++) {
            const int lo = span << 8, hi = lo + MAXC;
#pragma unroll
            for (int i = 0; i < 2; i++)
                *(float4*)&pbuf[w][(i*32 + lane)*4] = z4;
            __syncwarp();
            for (;;) {
                int j = jptr + lane;
                bool in = (j < cnt) && (sidx[j] < hi);
                unsigned msk = __ballot_sync(0xffffffffu, in);
                if (in) pbuf[w][sidx[j] - lo] = ssc[w][j];
                jptr += __popc(msk);
                if (msk != 0xffffffffu) break;
            }
            __syncwarp();
#pragma unroll
            for (int i = 0; i < 2; i++) {
                float4 vv = *(float4*)&pbuf[w][(i*32 + lane)*4];
                *(float4*)&arow_out[lo + (i*32 + lane)*4] = vv;
            }
            __syncwarp();
        }
    }
}

/* LayerNorm: one warp per row, no CTA barriers. */
__global__ __launch_bounds__(256) void ln_k(
    const float* __restrict__ x, const float* __restrict__ gamma,
    const float* __restrict__ beta, float* __restrict__ out)
{
    const int lane = threadIdx.x & 31, w = threadIdx.x >> 5;
    const int row = blockIdx.x * 8 + w;
    const float* xr = x + (size_t)row * 256;
    float4 v0 = *(const float4*)&xr[lane*4];
    float4 v1 = *(const float4*)&xr[128 + lane*4];
    float s = v0.x+v0.y+v0.z+v0.w + v1.x+v1.y+v1.z+v1.w;
#pragma unroll
    for (int off=16; off>=1; off>>=1) s += __shfl_xor_sync(0xffffffffu, s, off);
    const float mu = s * (1.f/256.f);
    float d0x=v0.x-mu, d0y=v0.y-mu, d0z=v0.z-mu, d0w=v0.w-mu;
    float d1x=v1.x-mu, d1y=v1.y-mu, d1z=v1.z-mu, d1w=v1.w-mu;
    float q2 = d0x*d0x+d0y*d0y+d0z*d0z+d0w*d0w + d1x*d1x+d1y*d1y+d1z*d1z+d1w*d1w;
#pragma unroll
    for (int off=16; off>=1; off>>=1) q2 += __shfl_xor_sync(0xffffffffu, q2, off);
    const float isd = 1.f / (sqrtf(q2 * (1.f/255.f)) + 1e-3f);
    float4 g0 = *(const float4*)&gamma[lane*4];
    float4 g1 = *(const float4*)&gamma[128 + lane*4];
    float4 b0 = *(const float4*)&beta[lane*4];
    float4 b1 = *(const float4*)&beta[128 + lane*4];
    float4 o0 = {d0x*isd*g0.x+b0.x, d0y*isd*g0.y+b0.y, d0z*isd*g0.z+b0.z, d0w*isd*g0.w+b0.w};
    float4 o1 = {d1x*isd*g1.x+b1.x, d1y*isd*g1.y+b1.y, d1z*isd*g1.z+b1.z, d1w*isd*g1.w+b1.w};
    float* orow = out + (size_t)row * 256;
    *(float4*)&orow[lane*4] = o0;
    *(float4*)&orow[128 + lane*4] = o1;
}

extern "C" void kernel_launch(void* const* d_in, const int* in_sizes, int n_in,
                              void* d_out, int out_size)
{
    const float* q    = (const float*)d_in[0];
    const float* k    = (const float*)d_in[1];
    const float* v    = (const float*)d_in[2];
    const float* adj  = (const float*)d_in[3];
    const float* Wq   = (const float*)d_in[5];
    const float* bq   = (const float*)d_in[6];
    const float* Wk   = (const float*)d_in[7];
    const float* bk   = (const float*)d_in[8];
    const float* Wv   = (const float*)d_in[9];
    const float* bv   = (const float*)d_in[10];
    const float* Wfc  = (const float*)d_in[11];
    const float* bfc  = (const float*)d_in[12];
    const float* Wfc1 = (const float*)d_in[13];
    const float* bfc1 = (const float*)d_in[14];
    const float* gamma = (const float*)d_in[15];
    const float* beta  = (const float*)d_in[16];

    float* out  = (float*)d_out;
    float* attn = out + (size_t)MROWS*DD;

    float *qp,*kp,*vp,*avp,*yp,*wcp,*bcp;
    cudaGetSymbolAddress((void**)&qp,  g_qp);
    cudaGetSymbolAddress((void**)&kp,  g_kp);
    cudaGetSymbolAddress((void**)&vp,  g_vp);
    cudaGetSymbolAddress((void**)&avp, g_av);
    cudaGetSymbolAddress((void**)&yp,  g_y);
    cudaGetSymbolAddress((void**)&wcp, g_wc);
    cudaGetSymbolAddress((void**)&bcp, g_bc);

    dim3 tb(256);
    gemm_qkv_k<<<dim3(DD/64, MROWS/64, 4), tb>>>(q, k, v, Wq, bq, Wk, bk, Wv, bv,
                                                 Wfc1, Wfc, bfc, bfc1,
                                                 qp, kp, vp, wcp, bcp);
    sattn_k<<<MROWS, tb>>>(qp, kp, vp, adj, attn, avp);
    gemm_fin_k<<<dim3(DD/64, MROWS/64), tb>>>(avp, q, wcp, Wfc1, bcp, yp);
    ln_k<<<MROWS/8, tb>>>(yp, gamma, beta, out);
}

// round 15
// speedup vs baseline: 1.0408x; 1.0408x over previous
#include <cuda_runtime.h>
#include <math.h>

#define BB 2
#define NN 2048
#define DD 256
#define MROWS (BB*NN)

typedef unsigned long long u64;
__device__ __forceinline__ u64 pk2(float lo, float hi) {
    u64 r; asm("mov.b64 %0,{%1,%2};" : "=l"(r) : "f"(lo), "f"(hi)); return r;
}
__device__ __forceinline__ void fma2(u64& d, u64 a, u64 b) {
    asm("fma.rn.f32x2 %0,%1,%2,%0;" : "+l"(d) : "l"(a), "l"(b));
}
__device__ __forceinline__ float2 up2(u64 v) {
    float lo, hi; asm("mov.b64 {%0,%1},%2;" : "=f"(lo), "=f"(hi) : "l"(v));
    float2 f; f.x = lo; f.y = hi; return f;
}

__device__ float g_qp[MROWS*DD];
__device__ float g_kp[MROWS*DD];
__device__ float g_vp[MROWS*DD];
__device__ float g_av[MROWS*DD];
__device__ float g_y [MROWS*DD];
__device__ float g_wc[DD*DD];
__device__ float g_bc[DD];

/* R5-proven 64x64 GEMM body: C = A@W^T + bias */
__device__ __forceinline__ void gemm_body(const float* __restrict__ A,
    const float* __restrict__ W, const float* __restrict__ bias,
    float* __restrict__ C, int K, int Nc)
{
    __shared__ float As[16*68], Bs[16*68];
    const int t = threadIdx.x;
    const int row0 = blockIdx.y * 64, col0 = blockIdx.x * 64;
    const int fr = t >> 2, fc = (t & 3) << 2;
    const int ty = t >> 4, tx = t & 15;
    u64 acc[4][2] = {};
    for (int k0 = 0; k0 < K; k0 += 16) {
        float4 a4 = *(const float4*)&A[(size_t)(row0+fr)*K + k0+fc];
        float4 w4 = *(const float4*)&W[(size_t)(col0+fr)*K + k0+fc];
        As[(fc+0)*68+fr]=a4.x; As[(fc+1)*68+fr]=a4.y; As[(fc+2)*68+fr]=a4.z; As[(fc+3)*68+fr]=a4.w;
        Bs[(fc+0)*68+fr]=w4.x; Bs[(fc+1)*68+fr]=w4.y; Bs[(fc+2)*68+fr]=w4.z; Bs[(fc+3)*68+fr]=w4.w;
        __syncthreads();
#pragma unroll
        for (int kk = 0; kk < 16; kk++) {
            float4 a = *(float4*)&As[kk*68 + (ty<<2)];
            ulonglong2 bb = *(ulonglong2*)&Bs[kk*68 + (tx<<2)];
            float av_[4]={a.x,a.y,a.z,a.w};
#pragma unroll
            for (int i=0;i<4;i++) {
                u64 aa = pk2(av_[i], av_[i]);
                fma2(acc[i][0], aa, bb.x);
                fma2(acc[i][1], aa, bb.y);
            }
        }
        __syncthreads();
    }
    const float4 bb = *(const float4*)&bias[col0 + (tx<<2)];
#pragma unroll
    for (int i=0;i<4;i++) {
        float2 c01 = up2(acc[i][0]), c23 = up2(acc[i][1]);
        float4 o = {c01.x+bb.x, c01.y+bb.y, c23.x+bb.z, c23.y+bb.w};
        *(float4*)&C[(size_t)(row0+(ty<<2)+i)*Nc + col0 + (tx<<2)] = o;
    }
}

/* Wc = Wfc1[:, :256] @ Wfc ; block (0,0) also computes bc */
__device__ __forceinline__ void wcomb_body(
    const float* __restrict__ Wfc1, const float* __restrict__ Wfc,
    const float* __restrict__ bfc, const float* __restrict__ bfc1,
    float* __restrict__ wc, float* __restrict__ bc)
{
    __shared__ float As[16*68], Bs[16*68];
    const int t = threadIdx.x;
    const int row0 = blockIdx.y*64, col0 = blockIdx.x*64;
    const int fr = t >> 2, fc = (t & 3) << 2;
    const int kr = t >> 4, cc = (t & 15) << 2;
    const int ty = t >> 4, tx = t & 15;
    u64 acc[4][2] = {};
    for (int k0 = 0; k0 < DD; k0 += 16) {
        float4 a4 = *(const float4*)&Wfc1[(size_t)(row0+fr)*(2*DD) + k0+fc];
        float4 b4 = *(const float4*)&Wfc[(size_t)(k0+kr)*DD + col0+cc];
        As[(fc+0)*68+fr]=a4.x; As[(fc+1)*68+fr]=a4.y; As[(fc+2)*68+fr]=a4.z; As[(fc+3)*68+fr]=a4.w;
        Bs[kr*68+cc+0]=b4.x; Bs[kr*68+cc+1]=b4.y; Bs[kr*68+cc+2]=b4.z; Bs[kr*68+cc+3]=b4.w;
        __syncthreads();
#pragma unroll
        for (int kk = 0; kk < 16; kk++) {
            float4 a = *(float4*)&As[kk*68 + (ty<<2)];
            ulonglong2 bb = *(ulonglong2*)&Bs[kk*68 + (tx<<2)];
            float av_[4]={a.x,a.y,a.z,a.w};
#pragma unroll
            for (int i=0;i<4;i++) {
                u64 aa = pk2(av_[i], av_[i]);
                fma2(acc[i][0], aa, bb.x);
                fma2(acc[i][1], aa, bb.y);
            }
        }
        __syncthreads();
    }
#pragma unroll
    for (int i=0;i<4;i++) {
        float2 c01 = up2(acc[i][0]), c23 = up2(acc[i][1]);
        float4 o = {c01.x, c01.y, c23.x, c23.y};
        *(float4*)&wc[(size_t)(row0+(ty<<2)+i)*DD + col0 + (tx<<2)] = o;
    }
    if (blockIdx.x == 0 && blockIdx.y == 0) {
        float s = bfc1[t];
        for (int k = 0; k < DD; k += 4) {
            float4 w = *(const float4*)&Wfc1[(size_t)t*(2*DD) + k];
            float4 b = *(const float4*)&bfc[k];
            s += w.x*b.x + w.y*b.y + w.z*b.z + w.w*b.w;
        }
        bc[t] = s;
    }
}

/* z=0..2: q/k/v projections; z=3 (blockIdx.y<4): Wc combine */
__global__ __launch_bounds__(256) void gemm_qkv_k(
    const float* __restrict__ q, const float* __restrict__ k, const float* __restrict__ v,
    const float* __restrict__ Wq, const float* __restrict__ bq,
    const float* __restrict__ Wk, const float* __restrict__ bk,
    const float* __restrict__ Wv, const float* __restrict__ bv,
    const float* __restrict__ Wfc1, const float* __restrict__ Wfc,
    const float* __restrict__ bfc, const float* __restrict__ bfc1,
    float* __restrict__ qp, float* __restrict__ kp, float* __restrict__ vp,
    float* __restrict__ wc, float* __restrict__ bc)
{
    if (blockIdx.z == 3) {
        if (blockIdx.y < 4)
            wcomb_body(Wfc1, Wfc, bfc, bfc1, wc, bc);
        return;
    }
    const float *A, *W, *bias; float* C;
    if (blockIdx.z == 0) { A=q; W=Wq; bias=bq; C=qp; }
    else if (blockIdx.z == 1) { A=k; W=Wk; bias=bk; C=kp; }
    else { A=v; W=Wv; bias=bv; C=vp; }
    gemm_body(A, W, bias, C, DD, DD);
}

/* y = av@wc^T + q@Wfc1[:,256:]^T + bc (K=512) */
__global__ __launch_bounds__(256) void gemm_fin_k(
    const float* __restrict__ av, const float* __restrict__ q,
    const float* __restrict__ wc, const float* __restrict__ Wfc1,
    const float* __restrict__ bc, float* __restrict__ y)
{
    __shared__ float As[16*68], Bs[16*68];
    const int t = threadIdx.x;
    const int row0 = blockIdx.y * 64, col0 = blockIdx.x * 64;
    const int fr = t >> 2, fc = (t & 3) << 2;
    const int ty = t >> 4, tx = t & 15;
    u64 acc[4][2] = {};
    for (int k0 = 0; k0 < 2*DD; k0 += 16) {
        float4 a4, w4;
        if (k0 < DD) {
            a4 = *(const float4*)&av[(size_t)(row0+fr)*DD + k0+fc];
            w4 = *(const float4*)&wc[(size_t)(col0+fr)*DD + k0+fc];
        } else {
            a4 = *(const float4*)&q[(size_t)(row0+fr)*DD + (k0-DD)+fc];
            w4 = *(const float4*)&Wfc1[(size_t)(col0+fr)*(2*DD) + k0+fc];
        }
        As[(fc+0)*68+fr]=a4.x; As[(fc+1)*68+fr]=a4.y; As[(fc+2)*68+fr]=a4.z; As[(fc+3)*68+fr]=a4.w;
        Bs[(fc+0)*68+fr]=w4.x; Bs[(fc+1)*68+fr]=w4.y; Bs[(fc+2)*68+fr]=w4.z; Bs[(fc+3)*68+fr]=w4.w;
        __syncthreads();
#pragma unroll
        for (int kk = 0; kk < 16; kk++) {
            float4 a = *(float4*)&As[kk*68 + (ty<<2)];
            ulonglong2 bb = *(ulonglong2*)&Bs[kk*68 + (tx<<2)];
            float av_[4]={a.x,a.y,a.z,a.w};
#pragma unroll
            for (int i=0;i<4;i++) {
                u64 aa = pk2(av_[i], av_[i]);
                fma2(acc[i][0], aa, bb.x);
                fma2(acc[i][1], aa, bb.y);
            }
        }
        __syncthreads();
    }
    const float4 bb = *(const float4*)&bc[col0 + (tx<<2)];
#pragma unroll
    for (int i=0;i<4;i++) {
        float2 c01 = up2(acc[i][0]), c23 = up2(acc[i][1]);
        float4 o = {c01.x+bb.x, c01.y+bb.y, c23.x+bb.z, c23.y+bb.w};
        *(float4*)&y[(size_t)(row0+(ty<<2)+i)*DD + col0 + (tx<<2)] = o;
    }
}

/* Sparse attention (R13-proven), dense single-pass output. */
#define MAXC 256
__global__ __launch_bounds__(256) void sattn_k(
    const float* __restrict__ qp, const float* __restrict__ kp,
    const float* __restrict__ vp, const float* __restrict__ adj,
    float* __restrict__ attn, float* __restrict__ av)
{
    __shared__ unsigned short sidx[NN];
    __shared__ float ssc[8][MAXC];
    __shared__ float pbuf[8][MAXC];
    __shared__ int warp_tot[8];
    __shared__ int s_cnt;

    const int t = threadIdx.x, lane = t & 31, w = t >> 5;
    const int grow = blockIdx.x;
    const int b = grow >> 11, row = grow & 2047;
    const float invT = 0.17677669529663687f;

    /* ordered compaction of adj-row nonzeros (sidx ascending) */
    {
        const float* arow = adj + (size_t)b*NN*NN + (size_t)row*NN;
        float4 a0 = *(const float4*)&arow[t*8];
        float4 a1 = *(const float4*)&arow[t*8 + 4];
        float va[8] = {a0.x,a0.y,a0.z,a0.w,a1.x,a1.y,a1.z,a1.w};
        int c = 0;
#pragma unroll
        for (int e = 0; e < 8; e++) c += (va[e] > 0.f);
        int sc = c;
#pragma unroll
        for (int off = 1; off < 32; off <<= 1) {
            int vsh = __shfl_up_sync(0xffffffffu, sc, off);
            if (lane >= off) sc += vsh;
        }
        int excl = sc - c;
        if (lane == 31) warp_tot[w] = sc;
        __syncthreads();
        int base = 0;
#pragma unroll
        for (int i = 0; i < 8; i++) if (i < w) base += warp_tot[i];
        int pos = base + excl;
#pragma unroll
        for (int e = 0; e < 8; e++)
            if (va[e] > 0.f) sidx[pos++] = (unsigned short)(t*8 + e);
        if (t == 0) {
            int tot = 0;
#pragma unroll
            for (int i = 0; i < 8; i++) tot += warp_tot[i];
            s_cnt = tot;
        }
        __syncthreads();
    }
    const int cnt = s_cnt;
    const int h = w;
    float* arow_out = attn + ((size_t)(h*BB + b)*NN + row)*NN;
    const float* qrow = &qp[((size_t)(b*NN + row))*DD + h*32];

    if (cnt == 0) {
        const float u = 1.0f/2048.0f;
        float4 uv = {u,u,u,u};
#pragma unroll
        for (int i = 0; i < 16; i++)
            *(float4*)&arow_out[(i*32 + lane)*4] = uv;
        float o = 0.f;
        for (int j = 0; j < NN; j++)
            o += vp[((size_t)(b*NN + j))*DD + h*32 + lane];
        av[((size_t)(b*NN + row))*DD + h*32 + lane] = o * u;
        return;
    }

    const bool fast = (cnt <= MAXC);
    if (!fast) {
        float4 z4 = {0.f,0.f,0.f,0.f};
#pragma unroll
        for (int i = 0; i < 16; i++)
            *(float4*)&arow_out[(i*32 + lane)*4] = z4;
        __syncwarp();
    }

    /* pass 1: scores (8 lanes/neighbor, 4 neighbors/iter), online (m,l) */
    const int sub = lane >> 3;
    const int dg  = (lane & 7) << 2;
    const float4 qq = *(const float4*)&qrow[dg];
    float m = -1e30f, l = 0.f;
    for (int base = 0; base < cnt; base += 4) {
        int j = base + sub;
        bool ok = (j < cnt);
        int n = sidx[ok ? j : 0];
        float4 kv = *(const float4*)&kp[((size_t)(b*NN + n))*DD + h*32 + dg];
        float part = qq.x*kv.x + qq.y*kv.y + qq.z*kv.z + qq.w*kv.w;
        part += __shfl_xor_sync(0xffffffffu, part, 4);
        part += __shfl_xor_sync(0xffffffffu, part, 2);
        part += __shfl_xor_sync(0xffffffffu, part, 1);
        if (ok && (lane & 7) == 0) {
            float s = part * invT;
            if (fast) ssc[w][j] = s; else arow_out[n] = s;
            float mn = fmaxf(m, s);
            l = l*__expf(m - mn) + __expf(s - mn);
            m = mn;
        }
    }
#pragma unroll
    for (int off = 16; off >= 1; off >>= 1) {
        float om = __shfl_xor_sync(0xffffffffu, m, off);
        float ol = __shfl_xor_sync(0xffffffffu, l, off);
        float mn = fmaxf(m, om);
        l = l*__expf(m - mn) + ol*__expf(om - mn);
        m = mn;
    }
    const float rinv = 1.0f / l;
    __syncwarp();

    /* pass 2: probabilities */
    if (fast) {
        for (int j = lane; j < cnt; j += 32)
            ssc[w][j] = __expf(ssc[w][j] - m) * rinv;
    } else {
        for (int j = lane; j < cnt; j += 32) {
            int n = sidx[j];
            arow_out[n] = __expf(arow_out[n] - m) * rinv;
        }
    }
    __syncwarp();

    /* P@V from compact probs */
    float o = 0.f;
    for (int base = 0; base < cnt; base += 32) {
        int j = base + lane;
        float p = 0.f; int n = 0;
        if (j < cnt) {
            n = sidx[j];
            p = fast ? ssc[w][j] : arow_out[n];
        }
#pragma unroll 4
        for (int jj = 0; jj < 32; jj++) {
            if (base + jj >= cnt) break;
            float pb = __shfl_sync(0xffffffffu, p, jj);
            int   nb = __shfl_sync(0xffffffffu, n, jj);
            o += pb * vp[((size_t)(b*NN + nb))*DD + h*32 + lane];
        }
    }
    av[((size_t)(b*NN + row))*DD + h*32 + lane] = o;

    /* dense single-pass output: sorted pointer walk over spans */
    if (fast) {
        float4 z4 = {0.f,0.f,0.f,0.f};
        int jptr = 0;
        for (int span = 0; span < NN/MAXC; span++) {
            const int lo = span << 8, hi = lo + MAXC;
#pragma unroll
            for (int i = 0; i < 2; i++)
                *(float4*)&pbuf[w][(i*32 + lane)*4] = z4;
            __syncwarp();
            for (;;) {
                int j = jptr + lane;
                bool in = (j < cnt) && (sidx[j] < hi);
                unsigned msk = __ballot_sync(0xffffffffu, in);
                if (in) pbuf[w][sidx[j] - lo] = ssc[w][j];
                jptr += __popc(msk);
                if (msk != 0xffffffffu) break;
            }
            __syncwarp();
#pragma unroll
            for (int i = 0; i < 2; i++) {
                float4 vv = *(float4*)&pbuf[w][(i*32 + lane)*4];
                *(float4*)&arow_out[lo + (i*32 + lane)*4] = vv;
            }
            __syncwarp();
        }
    }
}

/* LayerNorm: one warp per row, no CTA barriers (R14-proven). */
__global__ __launch_bounds__(256) void ln_k(
    const float* __restrict__ x, const float* __restrict__ gamma,
    const float* __restrict__ beta, float* __restrict__ out)
{
    const int lane = threadIdx.x & 31, w = threadIdx.x >> 5;
    const int row = blockIdx.x * 8 + w;
    const float* xr = x + (size_t)row * 256;
    float4 v0 = *(const float4*)&xr[lane*4];
    float4 v1 = *(const float4*)&xr[128 + lane*4];
    float s = v0.x+v0.y+v0.z+v0.w + v1.x+v1.y+v1.z+v1.w;
#pragma unroll
    for (int off=16; off>=1; off>>=1) s += __shfl_xor_sync(0xffffffffu, s, off);
    const float mu = s * (1.f/256.f);
    float d0x=v0.x-mu, d0y=v0.y-mu, d0z=v0.z-mu, d0w=v0.w-mu;
    float d1x=v1.x-mu, d1y=v1.y-mu, d1z=v1.z-mu, d1w=v1.w-mu;
    float q2 = d0x*d0x+d0y*d0y+d0z*d0z+d0w*d0w + d1x*d1x+d1y*d1y+d1z*d1z+d1w*d1w;
#pragma unroll
    for (int off=16; off>=1; off>>=1) q2 += __shfl_xor_sync(0xffffffffu, q2, off);
    const float isd = 1.f / (sqrtf(q2 * (1.f/255.f)) + 1e-3f);
    float4 g0 = *(const float4*)&gamma[lane*4];
    float4 g1 = *(const float4*)&gamma[128 + lane*4];
    float4 b0 = *(const float4*)&beta[lane*4];
    float4 b1 = *(const float4*)&beta[128 + lane*4];
    float4 o0 = {d0x*isd*g0.x+b0.x, d0y*isd*g0.y+b0.y, d0z*isd*g0.z+b0.z, d0w*isd*g0.w+b0.w};
    float4 o1 = {d1x*isd*g1.x+b1.x, d1y*isd*g1.y+b1.y, d1z*isd*g1.z+b1.z, d1w*isd*g1.w+b1.w};
    float* orow = out + (size_t)row * 256;
    *(float4*)&orow[lane*4] = o0;
    *(float4*)&orow[128 + lane*4] = o1;
}

extern "C" void kernel_launch(void* const* d_in, const int* in_sizes, int n_in,
                              void* d_out, int out_size)
{
    const float* q    = (const float*)d_in[0];
    const float* k    = (const float*)d_in[1];
    const float* v    = (const float*)d_in[2];
    const float* adj  = (const float*)d_in[3];
    const float* Wq   = (const float*)d_in[5];
    const float* bq   = (const float*)d_in[6];
    const float* Wk   = (const float*)d_in[7];
    const float* bk   = (const float*)d_in[8];
    const float* Wv   = (const float*)d_in[9];
    const float* bv   = (const float*)d_in[10];
    const float* Wfc  = (const float*)d_in[11];
    const float* bfc  = (const float*)d_in[12];
    const float* Wfc1 = (const float*)d_in[13];
    const float* bfc1 = (const float*)d_in[14];
    const float* gamma = (const float*)d_in[15];
    const float* beta  = (const float*)d_in[16];

    float* out  = (float*)d_out;
    float* attn = out + (size_t)MROWS*DD;

    float *qp,*kp,*vp,*avp,*yp,*wcp,*bcp;
    cudaGetSymbolAddress((void**)&qp,  g_qp);
    cudaGetSymbolAddress((void**)&kp,  g_kp);
    cudaGetSymbolAddress((void**)&vp,  g_vp);
    cudaGetSymbolAddress((void**)&avp, g_av);
    cudaGetSymbolAddress((void**)&yp,  g_y);
    cudaGetSymbolAddress((void**)&wcp, g_wc);
    cudaGetSymbolAddress((void**)&bcp, g_bc);

    dim3 tb(256);
    gemm_qkv_k<<<dim3(DD/64, MROWS/64, 4), tb>>>(q, k, v, Wq, bq, Wk, bk, Wv, bv,
                                                 Wfc1, Wfc, bfc, bfc1,
                                                 qp, kp, vp, wcp, bcp);
    sattn_k<<<MROWS, tb>>>(qp, kp, vp, adj, attn, avp);
    gemm_fin_k<<<dim3(DD/64, MROWS/64), tb>>>(avp, q, wcp, Wfc1, bcp, yp);
    ln_k<<<MROWS/8, tb>>>(yp, gamma, beta, out);
}